// round 16
// baseline (speedup 1.0000x reference)
#include <cuda_runtime.h>
#include <math.h>
#include <stdint.h>

#define Bq 64
#define Sq 48
#define Tq 48
#define Eq 256
#define Hq 512
#define Vq 32000
#define H3 1536

// ---------------- scratch (device globals; no runtime allocation) -------------
__device__ __align__(16) float g_gi_enc[Bq * Sq * H3];        // 18.9 MB
__device__ __align__(16) float g_gi_dec[Bq * (Tq - 1) * H3];  // 18.5 MB
__device__ __align__(16) float g_h0[2][Bq * Hq];
__device__ __align__(16) float g_h1[2][Bq * Hq];
__device__ __align__(16) float g_n0[Bq * Hq];
__device__ __align__(16) float g_ys[(Tq - 1) * Bq * Hq];      // 6.2 MB

// grid-barrier state (self-resetting across launches: arrive returns to 0,
// phase is monotonic and re-read as base each launch)
__device__ volatile unsigned g_phase;
__device__ unsigned g_arrive[2];

__device__ __forceinline__ float sigmoidf_(float x) { return 1.0f / (1.0f + expf(-x)); }

__device__ __forceinline__ uint32_t f2tf32(float f) {
    uint32_t u;
    asm("cvt.rna.tf32.f32 %0, %1;" : "=r"(u) : "f"(f));
    return u;
}

// packed dual-fp32 FMA (sm_100+): d = a*b + d elementwise on 2 packed floats
__device__ __forceinline__ void ffma2(unsigned long long& d,
                                      unsigned long long a, unsigned long long b) {
    asm("fma.rn.f32x2 %0, %1, %2, %0;" : "+l"(d) : "l"(a), "l"(b));
}

__device__ __forceinline__ float fold2(unsigned long long v) {
    float2 f;
    asm("mov.b64 {%0, %1}, %2;" : "=f"(f.x), "=f"(f.y) : "l"(v));
    return f.x + f.y;
}

// two-slot centralized grid barrier; CTA 0 is master. Safe because an arrival
// for barrier i+2 (same slot as i) requires observing phase >= base+i+2, which
// happens only after the master reset slot i%2 and published phase base+i+1.
__device__ __forceinline__ void gbar(unsigned idx, unsigned base) {
    __syncthreads();
    if (threadIdx.x == 0) {
        __threadfence();
        const unsigned slot = idx & 1u;
        if (blockIdx.x == 0) {
            while (*((volatile unsigned*)&g_arrive[slot]) < 127u) __nanosleep(64);
            g_arrive[slot] = 0u;
            __threadfence();
            g_phase = base + idx + 1u;
        } else {
            atomicAdd(&g_arrive[slot], 1u);
            while (g_phase - base < idx + 1u) __nanosleep(64);
            __threadfence();
        }
    }
    __syncthreads();
}

// stage 12 weight rows (this CTA's j-quad, all 3 gates, full K) into smem.
// smem row r = g*4+jj  <->  gmem row g*Hq + jb + jj.
__device__ __forceinline__ void stage12(float* dst, const float* __restrict__ W,
                                        int jb, int tid) {
#pragma unroll
    for (int f = tid; f < 12 * (Hq / 4); f += 256) {
        const int r = f >> 7, c = f & 127;
        const int wrow = (r >> 2) * Hq + jb + (r & 3);
        reinterpret_cast<float4*>(dst)[r * (Hq / 4) + c] =
            __ldg(reinterpret_cast<const float4*>(W + (size_t)wrow * Hq) + c);
    }
}

// ---------------- init kernels ------------------------------------------------
__global__ void zero_out0_kernel(float* __restrict__ out) {
    int i = blockIdx.x * blockDim.x + threadIdx.x;   // over B*V/4
    if (i < Bq * Vq / 4) {
        int b  = i / (Vq / 4);
        int v4 = i % (Vq / 4);
        reinterpret_cast<float4*>(out + (size_t)b * Tq * Vq)[v4] = make_float4(0.f, 0.f, 0.f, 0.f);
    }
}

// ---------------- gi0 = emb[tok] @ Wih^T + bih  (gathered SGEMM) --------------
__global__ __launch_bounds__(128) void embed_gi_kernel(
    const int* __restrict__ tokens, int rowlen, int rowstride,
    const float* __restrict__ emb,
    const float* __restrict__ W,    // [H3][E] row-major
    const float* __restrict__ bias, // [H3]
    int is_dec)
{
    __shared__ float As[8][64];
    __shared__ float Bs[8][128];
    float* __restrict__ out = is_dec ? g_gi_dec : g_gi_enc;

    const int tid = threadIdx.x;
    const int bm = blockIdx.y * 64;
    const int bn = blockIdx.x * 128;

    const int a_row = tid >> 1;            // 0..63
    const int a_col = (tid & 1) << 2;      // 0 or 4
    const int m = bm + a_row;
    const int tok = tokens[(m / rowlen) * rowstride + (m % rowlen)];
    const float* a_ptr = emb + (size_t)tok * Eq;
    const float* b_ptr = W + (size_t)(bn + tid) * Eq;

    const int rowT = tid >> 4;             // 0..7
    const int colT = tid & 15;             // 0..15

    float acc[8][8];
#pragma unroll
    for (int i = 0; i < 8; i++)
#pragma unroll
        for (int j = 0; j < 8; j++) acc[i][j] = 0.f;

    for (int k0 = 0; k0 < Eq; k0 += 8) {
        float4 av  = *reinterpret_cast<const float4*>(a_ptr + k0 + a_col);
        float4 bv0 = *reinterpret_cast<const float4*>(b_ptr + k0);
        float4 bv1 = *reinterpret_cast<const float4*>(b_ptr + k0 + 4);
        As[a_col + 0][a_row] = av.x; As[a_col + 1][a_row] = av.y;
        As[a_col + 2][a_row] = av.z; As[a_col + 3][a_row] = av.w;
        Bs[0][tid] = bv0.x; Bs[1][tid] = bv0.y; Bs[2][tid] = bv0.z; Bs[3][tid] = bv0.w;
        Bs[4][tid] = bv1.x; Bs[5][tid] = bv1.y; Bs[6][tid] = bv1.z; Bs[7][tid] = bv1.w;
        __syncthreads();
#pragma unroll
        for (int k = 0; k < 8; k++) {
            float a[8], b[8];
            *reinterpret_cast<float4*>(&a[0]) = *reinterpret_cast<const float4*>(&As[k][rowT * 8]);
            *reinterpret_cast<float4*>(&a[4]) = *reinterpret_cast<const float4*>(&As[k][rowT * 8 + 4]);
            *reinterpret_cast<float4*>(&b[0]) = *reinterpret_cast<const float4*>(&Bs[k][colT * 8]);
            *reinterpret_cast<float4*>(&b[4]) = *reinterpret_cast<const float4*>(&Bs[k][colT * 8 + 4]);
#pragma unroll
            for (int i = 0; i < 8; i++)
#pragma unroll
                for (int j = 0; j < 8; j++) acc[i][j] += a[i] * b[j];
        }
        __syncthreads();
    }

#pragma unroll
    for (int i = 0; i < 8; i++) {
        int mm = bm + rowT * 8 + i;
        float* op = out + (size_t)mm * H3 + bn + colT * 8;
        const float* bp = bias + bn + colT * 8;
#pragma unroll
        for (int j = 0; j < 8; j += 4) {
            float4 v;
            v.x = acc[i][j + 0] + bp[j + 0];
            v.y = acc[i][j + 1] + bp[j + 1];
            v.z = acc[i][j + 2] + bp[j + 2];
            v.w = acc[i][j + 3] + bp[j + 3];
            *reinterpret_cast<float4*>(op + j) = v;
        }
    }
}

// ---------------- persistent recurrence kernel --------------------------------
// 128 CTAs x 256 threads, one CTA per j-quad, resident for all 95 steps.
// Thread <-> (b, j): warp = 8 b x 4 j; k-serial packed-FFMA2 dots, weights in
// persistent smem (72 KB: l0 Whh + l1 Wih + l1 Whh rows of this j-quad),
// grid barrier between layer steps.
__global__ __launch_bounds__(256, 1) void gru_persistent(
    const int* __restrict__ slen,
    const float* __restrict__ eWhh0, const float* __restrict__ ebhh0,
    const float* __restrict__ eWih1, const float* __restrict__ ebih1,
    const float* __restrict__ eWhh1, const float* __restrict__ ebhh1,
    const float* __restrict__ dWhh0, const float* __restrict__ dbhh0,
    const float* __restrict__ dWih1, const float* __restrict__ dbih1,
    const float* __restrict__ dWhh1, const float* __restrict__ dbhh1)
{
    extern __shared__ float smem[];
    float* sW0  = smem;               // 12 x 512 (l0 Whh rows of j-quad)
    float* sWi1 = smem + 12 * Hq;     // 12 x 512 (l1 Wih)
    float* sWh1 = smem + 24 * Hq;     // 12 x 512 (l1 Whh)

    const int tid  = threadIdx.x;
    const int warp = tid >> 5;
    const int lane = tid & 31;
    const int jb = blockIdx.x << 2;
    const int jj = lane & 3;
    const int b  = (warp << 3) + (lane >> 2);   // 0..63
    const int j  = jb + jj;

    __shared__ unsigned s_base;
    if (tid == 0) s_base = g_phase;   // safe: phase can't advance before all arrive

    // zero h state (exactly one element per thread: 128*256 == Bq*Hq)
    const int gid = blockIdx.x * 256 + tid;
    g_h0[0][gid] = 0.f;
    g_h1[0][gid] = 0.f;
    __syncthreads();
    const unsigned base = s_base;

    // stage encoder weights (CTA-local smem; gbar below includes the sync)
    stage12(sW0,  eWhh0, jb, tid);
    stage12(sWi1, eWih1, jb, tid);
    stage12(sWh1, eWhh1, jb, tid);

    unsigned bar = 0;
    gbar(bar++, base);                // h-zero visible everywhere

    const int slen_b = slen[b];
    int cur = 0;

#pragma unroll 1
    for (int step = 0; step < Sq + Tq - 1; step++) {
        const bool enc = step < Sq;
        const int t = enc ? step : step - Sq;

        if (step == Sq) {             // phase switch: restage decoder weights
            __syncthreads();          // CTA done reading its own enc smem
            stage12(sW0,  dWhh0, jb, tid);
            stage12(sWi1, dWih1, jb, tid);
            stage12(sWh1, dWhh1, jb, tid);
            __syncthreads();
        }

        const float* gi_t = enc ? (g_gi_enc + (size_t)t * H3)
                                : (g_gi_dec + (size_t)t * H3);
        const int bstride = enc ? Sq * H3 : (Tq - 1) * H3;
        const float* bhh0 = enc ? ebhh0 : dbhh0;
        const float* bih1 = enc ? ebih1 : dbih1;
        const float* bhh1 = enc ? ebhh1 : dbhh1;
        const bool msk = enc ? (t < slen_b) : true;

        // ---- layer 0 ----
        {
            const float* __restrict__ hrow = g_h0[cur] + b * Hq;
            const float* w0 = sW0 + (0 + jj) * Hq;
            const float* w1 = sW0 + (4 + jj) * Hq;
            const float* w2 = sW0 + (8 + jj) * Hq;
            unsigned long long a0 = 0ull, a1 = 0ull, a2 = 0ull;
#pragma unroll 16
            for (int k = 0; k < Hq; k += 4) {
                ulonglong2 hv = *reinterpret_cast<const ulonglong2*>(hrow + k);
                ulonglong2 v0 = *reinterpret_cast<const ulonglong2*>(w0 + k);
                ulonglong2 v1 = *reinterpret_cast<const ulonglong2*>(w1 + k);
                ulonglong2 v2 = *reinterpret_cast<const ulonglong2*>(w2 + k);
                ffma2(a0, hv.x, v0.x); ffma2(a0, hv.y, v0.y);
                ffma2(a1, hv.x, v1.x); ffma2(a1, hv.y, v1.y);
                ffma2(a2, hv.x, v2.x); ffma2(a2, hv.y, v2.y);
            }
            const float A0 = fold2(a0), A1 = fold2(a1), A2 = fold2(a2);
            const float* gi = gi_t + (size_t)b * bstride;
            float r = sigmoidf_(gi[j]          + A0 + bhh0[j]);
            float z = sigmoidf_(gi[Hq + j]     + A1 + bhh0[Hq + j]);
            float n = tanhf(gi[2 * Hq + j] + r * (A2 + bhh0[2 * Hq + j]));
            float hp = hrow[j];
            float hn = (1.f - z) * n + z * hp;
            g_n0[b * Hq + j] = hn;                       // raw output feeds layer 1
            g_h0[cur ^ 1][b * Hq + j] = msk ? hn : hp;   // masked carry
        }
        gbar(bar++, base);

        // ---- layer 1 ----
        {
            const float* __restrict__ xrow = g_n0 + b * Hq;
            const float* __restrict__ hrow = g_h1[cur] + b * Hq;
            const float* wi0 = sWi1 + (0 + jj) * Hq;
            const float* wi1 = sWi1 + (4 + jj) * Hq;
            const float* wi2 = sWi1 + (8 + jj) * Hq;
            const float* wh0 = sWh1 + (0 + jj) * Hq;
            const float* wh1 = sWh1 + (4 + jj) * Hq;
            const float* wh2 = sWh1 + (8 + jj) * Hq;
            unsigned long long x0 = 0ull, x1 = 0ull, x2 = 0ull;
            unsigned long long h0a = 0ull, h1a = 0ull, h2a = 0ull;
#pragma unroll 8
            for (int k = 0; k < Hq; k += 4) {
                ulonglong2 xv = *reinterpret_cast<const ulonglong2*>(xrow + k);
                ulonglong2 hv = *reinterpret_cast<const ulonglong2*>(hrow + k);
                ulonglong2 i0 = *reinterpret_cast<const ulonglong2*>(wi0 + k);
                ulonglong2 i1 = *reinterpret_cast<const ulonglong2*>(wi1 + k);
                ulonglong2 i2 = *reinterpret_cast<const ulonglong2*>(wi2 + k);
                ulonglong2 h0v = *reinterpret_cast<const ulonglong2*>(wh0 + k);
                ulonglong2 h1v = *reinterpret_cast<const ulonglong2*>(wh1 + k);
                ulonglong2 h2v = *reinterpret_cast<const ulonglong2*>(wh2 + k);
                ffma2(x0, xv.x, i0.x);  ffma2(x0, xv.y, i0.y);
                ffma2(x1, xv.x, i1.x);  ffma2(x1, xv.y, i1.y);
                ffma2(x2, xv.x, i2.x);  ffma2(x2, xv.y, i2.y);
                ffma2(h0a, hv.x, h0v.x); ffma2(h0a, hv.y, h0v.y);
                ffma2(h1a, hv.x, h1v.x); ffma2(h1a, hv.y, h1v.y);
                ffma2(h2a, hv.x, h2v.x); ffma2(h2a, hv.y, h2v.y);
            }
            const float AX0 = fold2(x0), AX1 = fold2(x1), AX2 = fold2(x2);
            const float AH0 = fold2(h0a), AH1 = fold2(h1a), AH2 = fold2(h2a);
            float r = sigmoidf_(AX0 + bih1[j]          + AH0 + bhh1[j]);
            float z = sigmoidf_(AX1 + bih1[Hq + j]     + AH1 + bhh1[Hq + j]);
            float n = tanhf(AX2 + bih1[2 * Hq + j] + r * (AH2 + bhh1[2 * Hq + j]));
            float hp = hrow[j];
            float hn = (1.f - z) * n + z * hp;
            g_h1[cur ^ 1][b * Hq + j] = msk ? hn : hp;
            if (!enc) g_ys[((size_t)t * Bq + b) * Hq + j] = hn;
        }
        gbar(bar++, base);

        cur ^= 1;
    }
}

// ---------------- final FC (tf32 tensor cores) --------------------------------
__global__ __launch_bounds__(256) void fc_tf32_kernel(
    const float* __restrict__ W,    // [V][H]
    const float* __restrict__ bias, // [V]
    float* __restrict__ out)
{
    __shared__ float As[64][20];    // padded stride 20: conflict-free frag loads
    __shared__ float Bs[128][20];

    const int tid  = threadIdx.x;
    const int warp = tid >> 5;
    const int lane = tid & 31;
    const int g    = lane >> 2;     // groupID 0..7
    const int tg   = lane & 3;      // threadID_in_group 0..3

    const int bm = blockIdx.x * 64;     // = t-slab (64 rows = one t)
    const int bn = blockIdx.y * 128;
    const int wm = (warp & 1) * 32;
    const int wn = (warp >> 1) * 32;

    const int ar = tid >> 2;            // 0..63
    const int ac = (tid & 3) << 2;      // 0,4,8,12
    const int br = tid >> 1;            // 0..127
    const int bc = (tid & 1) << 3;      // 0 or 8

    const float* a_ptr = g_ys + (size_t)(bm + ar) * Hq + ac;
    const float* b_ptr = W + (size_t)(bn + br) * Hq + bc;

    float c[2][4][4];
#pragma unroll
    for (int am = 0; am < 2; am++)
#pragma unroll
        for (int an = 0; an < 4; an++)
#pragma unroll
            for (int i = 0; i < 4; i++) c[am][an][i] = 0.f;

    for (int k0 = 0; k0 < Hq; k0 += 16) {
        float4 av  = *reinterpret_cast<const float4*>(a_ptr + k0);
        float4 bv0 = __ldg(reinterpret_cast<const float4*>(b_ptr + k0));
        float4 bv1 = __ldg(reinterpret_cast<const float4*>(b_ptr + k0 + 4));
        __syncthreads();
        As[ar][ac + 0] = __uint_as_float(f2tf32(av.x));
        As[ar][ac + 1] = __uint_as_float(f2tf32(av.y));
        As[ar][ac + 2] = __uint_as_float(f2tf32(av.z));
        As[ar][ac + 3] = __uint_as_float(f2tf32(av.w));
        Bs[br][bc + 0] = __uint_as_float(f2tf32(bv0.x));
        Bs[br][bc + 1] = __uint_as_float(f2tf32(bv0.y));
        Bs[br][bc + 2] = __uint_as_float(f2tf32(bv0.z));
        Bs[br][bc + 3] = __uint_as_float(f2tf32(bv0.w));
        Bs[br][bc + 4] = __uint_as_float(f2tf32(bv1.x));
        Bs[br][bc + 5] = __uint_as_float(f2tf32(bv1.y));
        Bs[br][bc + 6] = __uint_as_float(f2tf32(bv1.z));
        Bs[br][bc + 7] = __uint_as_float(f2tf32(bv1.w));
        __syncthreads();

#pragma unroll
        for (int ks = 0; ks < 2; ks++) {
            const int kk = ks * 8;
            uint32_t a[2][4];
#pragma unroll
            for (int am = 0; am < 2; am++) {
                const int r0 = wm + am * 16;
                a[am][0] = __float_as_uint(As[r0 + g    ][kk + tg    ]);
                a[am][1] = __float_as_uint(As[r0 + g + 8][kk + tg    ]);
                a[am][2] = __float_as_uint(As[r0 + g    ][kk + tg + 4]);
                a[am][3] = __float_as_uint(As[r0 + g + 8][kk + tg + 4]);
            }
            uint32_t b[4][2];
#pragma unroll
            for (int an = 0; an < 4; an++) {
                const int n0 = wn + an * 8;
                b[an][0] = __float_as_uint(Bs[n0 + g][kk + tg    ]);
                b[an][1] = __float_as_uint(Bs[n0 + g][kk + tg + 4]);
            }
#pragma unroll
            for (int am = 0; am < 2; am++)
#pragma unroll
                for (int an = 0; an < 4; an++) {
                    asm volatile(
                        "mma.sync.aligned.m16n8k8.row.col.f32.tf32.tf32.f32 "
                        "{%0,%1,%2,%3}, {%4,%5,%6,%7}, {%8,%9}, {%0,%1,%2,%3};"
                        : "+f"(c[am][an][0]), "+f"(c[am][an][1]),
                          "+f"(c[am][an][2]), "+f"(c[am][an][3])
                        : "r"(a[am][0]), "r"(a[am][1]), "r"(a[am][2]), "r"(a[am][3]),
                          "r"(b[an][0]), "r"(b[an][1]));
                }
        }
    }

#pragma unroll
    for (int am = 0; am < 2; am++) {
#pragma unroll
        for (int an = 0; an < 4; an++) {
            const int n0 = bn + wn + an * 8 + tg * 2;
            const float bx = __ldg(bias + n0);
            const float by = __ldg(bias + n0 + 1);
#pragma unroll
            for (int rr = 0; rr < 2; rr++) {
                const int mm = bm + wm + am * 16 + g + rr * 8;   // = t*64 + b
                const int tt = mm >> 6;
                const int bb = mm & 63;
                float2 v;
                v.x = c[am][an][rr * 2 + 0] + bx;
                v.y = c[am][an][rr * 2 + 1] + by;
                *reinterpret_cast<float2*>(
                    out + ((size_t)bb * Tq + (tt + 1)) * Vq + n0) = v;
            }
        }
    }
}

// -----------------------------------------------------------------------------
extern "C" void kernel_launch(void* const* d_in, const int* in_sizes, int n_in,
                              void* d_out, int out_size)
{
    const int*   source  = (const int*)d_in[0];
    const int*   target  = (const int*)d_in[1];
    const int*   slen    = (const int*)d_in[2];
    const float* enc_emb = (const float*)d_in[3];
    const float* eWih0 = (const float*)d_in[4];
    const float* eWhh0 = (const float*)d_in[5];
    const float* ebih0 = (const float*)d_in[6];
    const float* ebhh0 = (const float*)d_in[7];
    const float* eWih1 = (const float*)d_in[8];
    const float* eWhh1 = (const float*)d_in[9];
    const float* ebih1 = (const float*)d_in[10];
    const float* ebhh1 = (const float*)d_in[11];
    const float* dec_emb = (const float*)d_in[12];
    const float* dWih0 = (const float*)d_in[13];
    const float* dWhh0 = (const float*)d_in[14];
    const float* dbih0 = (const float*)d_in[15];
    const float* dbhh0 = (const float*)d_in[16];
    const float* dWih1 = (const float*)d_in[17];
    const float* dWhh1 = (const float*)d_in[18];
    const float* dbih1 = (const float*)d_in[19];
    const float* dbhh1 = (const float*)d_in[20];
    const float* fcW   = (const float*)d_in[21];
    const float* fcb   = (const float*)d_in[22];
    float* out = (float*)d_out;

    const int persist_smem = 36 * Hq * (int)sizeof(float);   // 73728 B
    cudaFuncSetAttribute(gru_persistent,
                         cudaFuncAttributeMaxDynamicSharedMemorySize, persist_smem);

    // precompute layer-0 input-side gates for all timesteps (gathered GEMMs)
    {
        dim3 ge(H3 / 128, Sq * Bq / 64);   // (12, 48)
        embed_gi_kernel<<<ge, 128>>>(source, Sq, Sq, enc_emb, eWih0, ebih0, 0);
        dim3 gd(H3 / 128, (Tq - 1) * Bq / 64);   // (12, 47)
        embed_gi_kernel<<<gd, 128>>>(target, Tq - 1, Tq, dec_emb, dWih0, dbih0, 1);
    }

    // entire recurrence (enc 48 + dec 47 steps) in one persistent kernel
    gru_persistent<<<128, 256, persist_smem>>>(
        slen,
        eWhh0, ebhh0, eWih1, ebih1, eWhh1, ebhh1,
        dWhh0, dbhh0, dWih1, dbih1, dWhh1, dbhh1);

    // output: out[:,0,:] = 0; out[:,1:,:] = ys @ fc_W^T + fc_b (tf32 MMA)
    zero_out0_kernel<<<(Bq * Vq / 4 + 255) / 256, 256>>>(out);
    dim3 gf((Tq - 1) * Bq / 64, Vq / 128);   // (47, 250)
    fc_tf32_kernel<<<gf, 256>>>(fcW, fcb, out);
}